// round 16
// baseline (speedup 1.0000x reference)
#include <cuda_runtime.h>
#include <cuda_bf16.h>
#include <cstdint>

#define DIM 64
#define TSTEPS 1000
#define BATCH 1024
#define MSZ (DIM*DIM)   // 4096
#define TLOOP 8

// squaring table M^(2^j), j = 0..9, fp32
__device__ float g_sq[10 * MSZ];
// two-level tables: low[r] = M^r (r<32), high[q] = M^(32q) (q<32)
__device__ float g_low[32 * MSZ];
__device__ float g_high[32 * MSZ];
// bf16 2-way split of M^t: [t][plane][i*64+j], planes hi/lo
__device__ __align__(16) __nv_bfloat16 g_powsb[TSTEPS * 2 * MSZ];
// bf16 2-way split of x0: [plane][b*64+j]
__device__ __align__(16) __nv_bfloat16 g_x0s[2 * BATCH * DIM];

// ===========================================================================
// helpers
// ===========================================================================
__device__ __forceinline__ uint32_t smem_to_u32(const void* p) {
    uint32_t a;
    asm("{ .reg .u64 t; cvta.to.shared.u64 t, %1; cvt.u32.u64 %0, t; }"
        : "=r"(a) : "l"(p));
    return a;
}

__device__ __forceinline__ void split2(float v, __nv_bfloat16& h, __nv_bfloat16& l) {
    h = __float2bfloat16(v);
    l = __float2bfloat16(v - __bfloat162float(h));
}
__device__ __forceinline__ void split3(float v, __nv_bfloat16& h,
                                       __nv_bfloat16& m, __nv_bfloat16& l) {
    h = __float2bfloat16(v);
    float r = v - __bfloat162float(h);
    m = __float2bfloat16(r);
    l = __float2bfloat16(r - __bfloat162float(m));
}

#define LDSM_X4(r, addr) \
    asm volatile("ldmatrix.sync.aligned.m8n8.x4.shared.b16 {%0,%1,%2,%3}, [%4];" \
        : "=r"((r)[0]), "=r"((r)[1]), "=r"((r)[2]), "=r"((r)[3]) : "r"(addr))

#define LDSM_X4_T(r, addr) \
    asm volatile("ldmatrix.sync.aligned.m8n8.x4.trans.shared.b16 {%0,%1,%2,%3}, [%4];" \
        : "=r"((r)[0]), "=r"((r)[1]), "=r"((r)[2]), "=r"((r)[3]) : "r"(addr))

#define MMA16816(d, a, b) \
    asm volatile("mma.sync.aligned.m16n8k16.row.col.f32.bf16.bf16.f32 " \
        "{%0,%1,%2,%3}, {%4,%5,%6,%7}, {%8,%9}, {%0,%1,%2,%3};" \
        : "+f"((d)[0]), "+f"((d)[1]), "+f"((d)[2]), "+f"((d)[3]) \
        : "r"((a)[0]), "r"((a)[1]), "r"((a)[2]), "r"((a)[3]), \
          "r"((b)[0]), "r"((b)[1]))

// cp.async: 16B global -> shared, bypassing registers
#define CP_ASYNC16(dst_u32, src_ptr) \
    asm volatile("cp.async.ca.shared.global [%0], [%1], 16;" \
        :: "r"(dst_u32), "l"(src_ptr))
#define CP_COMMIT()  asm volatile("cp.async.commit_group;" ::: "memory")
#define CP_WAIT0()   asm volatile("cp.async.wait_group 0;" ::: "memory")

#define PL 9216     // plane bytes: 64 rows * 144

// ===========================================================================
// mm64_tc3: C = A @ B via 3-way bf16 split + 6-cross HMMA (~1.5e-8/multiply).
// 256 threads. C may alias A/B. scr: 6 planes = 55296B.
// ===========================================================================
#define SCR3_SZ (6 * PL)
__device__ void mm64_tc3(const float* A, const float* B, float* C, char* scr) {
    uint32_t scrb = smem_to_u32(scr);
    int tid = threadIdx.x;
    __syncthreads();
#pragma unroll
    for (int q = 0; q < 8; q++) {
        int e2 = tid + 256 * q;
        int row = e2 >> 5, cp = e2 & 31;
        float2 a = *(const float2*)(A + row * 64 + cp * 2);
        float2 b = *(const float2*)(B + row * 64 + cp * 2);
        __nv_bfloat16 h0, m0, l0, h1, m1, l1;
        split3(a.x, h0, m0, l0); split3(a.y, h1, m1, l1);
        *(__nv_bfloat162*)(scr + 0 * PL + row * 144 + cp * 4) = {h0, h1};
        *(__nv_bfloat162*)(scr + 1 * PL + row * 144 + cp * 4) = {m0, m1};
        *(__nv_bfloat162*)(scr + 2 * PL + row * 144 + cp * 4) = {l0, l1};
        split3(b.x, h0, m0, l0); split3(b.y, h1, m1, l1);
        *(__nv_bfloat162*)(scr + 3 * PL + row * 144 + cp * 4) = {h0, h1};
        *(__nv_bfloat162*)(scr + 4 * PL + row * 144 + cp * 4) = {m0, m1};
        *(__nv_bfloat162*)(scr + 5 * PL + row * 144 + cp * 4) = {l0, l1};
    }
    __syncthreads();
    int w = tid >> 5, lane = tid & 31;
    int mt = w & 3, nh = w >> 2;
    float acc[4][4];
#pragma unroll
    for (int nt = 0; nt < 4; nt++)
#pragma unroll
        for (int c = 0; c < 4; c++) acc[nt][c] = 0.0f;

    uint32_t a_base = scrb + (16 * mt + (lane & 15)) * 144 + ((lane >> 4) * 8) * 2;
#pragma unroll
    for (int k0 = 0; k0 < 64; k0 += 16) {
        uint32_t aH[4], aM[4], aL[4];
        LDSM_X4(aH, a_base + k0 * 2);
        LDSM_X4(aM, a_base + PL + k0 * 2);
        LDSM_X4(aL, a_base + 2 * PL + k0 * 2);
#pragma unroll
        for (int np = 0; np < 2; np++) {
            int n0 = 32 * nh + np * 16;
            uint32_t b_addr = scrb + 3 * PL + (k0 + (lane & 15)) * 144
                            + (n0 + (lane >> 4) * 8) * 2;
            uint32_t bH[4], bM[4], bL[4];
            LDSM_X4_T(bH, b_addr);
            LDSM_X4_T(bM, b_addr + PL);
            LDSM_X4_T(bL, b_addr + 2 * PL);
#pragma unroll
            for (int h2 = 0; h2 < 2; h2++) {
                float* d = acc[2 * np + h2];
                MMA16816(d, aH, &bH[2 * h2]);
                MMA16816(d, aH, &bM[2 * h2]);
                MMA16816(d, aM, &bH[2 * h2]);
                MMA16816(d, aH, &bL[2 * h2]);
                MMA16816(d, aM, &bM[2 * h2]);
                MMA16816(d, aL, &bH[2 * h2]);
            }
        }
    }
    __syncthreads();
    int g = lane >> 2, qd = lane & 3;
#pragma unroll
    for (int nt = 0; nt < 4; nt++) {
        int col = 32 * nh + 8 * nt + 2 * qd;
        *(float2*)(C + (16 * mt + g) * 64 + col) = make_float2(acc[nt][0], acc[nt][1]);
        *(float2*)(C + (16 * mt + g + 8) * 64 + col) = make_float2(acc[nt][2], acc[nt][3]);
    }
    __syncthreads();
}

// ===========================================================================
// mm64_tc2: C = A @ B via 2-way bf16 split + 3-cross HMMA (~4e-6/multiply).
// 256 threads. scr: 4 planes = 36864B.
// ===========================================================================
#define SCR2_SZ (4 * PL)
__device__ void mm64_tc2(const float* A, const float* B, float* C, char* scr) {
    uint32_t scrb = smem_to_u32(scr);
    int tid = threadIdx.x;
    __syncthreads();
#pragma unroll
    for (int q = 0; q < 8; q++) {
        int e2 = tid + 256 * q;
        int row = e2 >> 5, cp = e2 & 31;
        float2 a = *(const float2*)(A + row * 64 + cp * 2);
        float2 b = *(const float2*)(B + row * 64 + cp * 2);
        __nv_bfloat16 h0, l0, h1, l1;
        split2(a.x, h0, l0); split2(a.y, h1, l1);
        *(__nv_bfloat162*)(scr + 0 * PL + row * 144 + cp * 4) = {h0, h1};
        *(__nv_bfloat162*)(scr + 1 * PL + row * 144 + cp * 4) = {l0, l1};
        split2(b.x, h0, l0); split2(b.y, h1, l1);
        *(__nv_bfloat162*)(scr + 2 * PL + row * 144 + cp * 4) = {h0, h1};
        *(__nv_bfloat162*)(scr + 3 * PL + row * 144 + cp * 4) = {l0, l1};
    }
    __syncthreads();
    int w = tid >> 5, lane = tid & 31;
    int mt = w & 3, nh = w >> 2;
    float acc[4][4];
#pragma unroll
    for (int nt = 0; nt < 4; nt++)
#pragma unroll
        for (int c = 0; c < 4; c++) acc[nt][c] = 0.0f;

    uint32_t a_base = scrb + (16 * mt + (lane & 15)) * 144 + ((lane >> 4) * 8) * 2;
#pragma unroll
    for (int k0 = 0; k0 < 64; k0 += 16) {
        uint32_t aH[4], aL[4];
        LDSM_X4(aH, a_base + k0 * 2);
        LDSM_X4(aL, a_base + PL + k0 * 2);
#pragma unroll
        for (int np = 0; np < 2; np++) {
            int n0 = 32 * nh + np * 16;
            uint32_t b_addr = scrb + 2 * PL + (k0 + (lane & 15)) * 144
                            + (n0 + (lane >> 4) * 8) * 2;
            uint32_t bH[4], bL[4];
            LDSM_X4_T(bH, b_addr);
            LDSM_X4_T(bL, b_addr + PL);
#pragma unroll
            for (int h2 = 0; h2 < 2; h2++) {
                float* d = acc[2 * np + h2];
                MMA16816(d, aH, &bH[2 * h2]);
                MMA16816(d, aH, &bL[2 * h2]);
                MMA16816(d, aL, &bH[2 * h2]);
            }
        }
    }
    __syncthreads();
    int g = lane >> 2, qd = lane & 3;
#pragma unroll
    for (int nt = 0; nt < 4; nt++) {
        int col = 32 * nh + 8 * nt + 2 * qd;
        *(float2*)(C + (16 * mt + g) * 64 + col) = make_float2(acc[nt][0], acc[nt][1]);
        *(float2*)(C + (16 * mt + g + 8) * 64 + col) = make_float2(acc[nt][2], acc[nt][3]);
    }
    __syncthreads();
}

// ===========================================================================
// Kernel 1 (grid 257): CTA 0: M = expm(K) (deg-8 PS Taylor) + 9 squarings
// (3-way tc). CTAs 1..256: x0 bf16 split.
// ===========================================================================
#define L1_SMEM (5 * MSZ * 4 + SCR3_SZ)
__global__ void expm_sq_kernel(const float* __restrict__ Kin,
                               const float* __restrict__ inputs) {
    int tid = threadIdx.x;
    if (blockIdx.x > 0) {   // x0 split
        int idx = (int)(blockIdx.x - 1) * 256 + tid;   // 0..65535
        int b = idx >> 6, j = idx & 63;
        float v = inputs[(size_t)b * (TSTEPS * DIM) + j];
        __nv_bfloat16 h, l;
        split2(v, h, l);
        g_x0s[idx] = h;
        g_x0s[65536 + idx] = l;
        return;
    }

    extern __shared__ float smf[];
    float* sK  = smf;
    float* sK2 = smf + MSZ;
    float* sK3 = smf + 2 * MSZ;
    float* sS  = smf + 3 * MSZ;
    float* sT  = smf + 4 * MSZ;
    char* scr = (char*)(smf + 5 * MSZ);

    // 1/n! for n = 0..8
    const float c[9] = {
        1.0f, 1.0f, 0.5f,
        1.6666666666666666e-1f, 4.1666666666666664e-2f, 8.3333333333333332e-3f,
        1.3888888888888889e-3f, 1.9841269841269841e-4f, 2.4801587301587302e-5f
    };

#pragma unroll
    for (int q = 0; q < 16; q++) sK[tid + 256 * q] = Kin[tid + 256 * q];

    mm64_tc3(sK, sK, sK2, scr);     // K^2
    mm64_tc3(sK2, sK, sK3, scr);    // K^3

    // S = B2 = c6 I + c7 K + c8 K^2
#pragma unroll
    for (int q = 0; q < 16; q++) {
        int e = tid + 256 * q;
        int i = e >> 6, j = e & 63;
        sS[e] = (i == j ? c[6] : 0.0f) + c[7] * sK[e] + c[8] * sK2[e];
    }
    __syncthreads();
    for (int m = 1; m >= 0; m--) {
        mm64_tc3(sK3, sS, sT, scr);
#pragma unroll
        for (int q = 0; q < 16; q++) {
            int e = tid + 256 * q;
            int i = e >> 6, j = e & 63;
            sS[e] = sT[e] + (i == j ? c[3 * m] : 0.0f)
                  + c[3 * m + 1] * sK[e] + c[3 * m + 2] * sK2[e];
        }
        __syncthreads();
    }

    // sS = M. Store sq[0], then 9 squarings (in-place safe).
#pragma unroll
    for (int q = 0; q < 16; q++) g_sq[tid + 256 * q] = sS[tid + 256 * q];
    for (int j = 1; j <= 9; j++) {
        mm64_tc3(sS, sS, sS, scr);
#pragma unroll
        for (int q = 0; q < 16; q++)
            g_sq[j * MSZ + tid + 256 * q] = sS[tid + 256 * q];
    }
}

// ===========================================================================
// Kernel 2 (grid 64): two-level tables (3-way tc).
// ===========================================================================
#define L_TB_SMEM (MSZ * 4 + SCR3_SZ)
__global__ void tables_kernel() {
    extern __shared__ float smf[];
    float* sA = smf;
    char* scr = (char*)(smf + MSZ);
    int bid = blockIdx.x;
    int tid = threadIdx.x;

    int n = bid & 31;
    int base = (bid < 32) ? 0 : 5;
    float* dst = (bid < 32 ? g_low : g_high) + (size_t)n * MSZ;

    if (n == 0) {
#pragma unroll
        for (int q = 0; q < 16; q++) {
            int e = tid + 256 * q;
            dst[e] = ((e >> 6) == (e & 63)) ? 1.0f : 0.0f;
        }
        return;
    }

    int j0 = __ffs(n) - 1;
    const float* first = g_sq + (size_t)(base + j0) * MSZ;
    bool in_smem = false;
    for (int j = j0 + 1; j < 5; j++) {
        if ((n >> j) & 1) {
            const float* fac = g_sq + (size_t)(base + j) * MSZ;
            mm64_tc3(in_smem ? sA : first, fac, sA, scr);
            in_smem = true;
        }
    }
    const float* res = in_smem ? sA : first;
#pragma unroll
    for (int q = 0; q < 16; q++) {
        int e = tid + 256 * q;
        dst[e] = res[e];
    }
}

// ===========================================================================
// Kernel 3 (grid 1000): M^t = high[t>>5] @ low[t&31] (one 2-way tc multiply),
// write bf16 hi/lo split.
// ===========================================================================
#define L_PW_SMEM (MSZ * 4 + SCR2_SZ)
__global__ void power_kernel() {
    extern __shared__ float smf[];
    float* sA = smf;
    char* scr = (char*)(smf + MSZ);
    int t = blockIdx.x;
    int tid = threadIdx.x;
    int q5 = t >> 5, r = t & 31;

    mm64_tc2(g_high + (size_t)q5 * MSZ, g_low + (size_t)r * MSZ, sA, scr);

    size_t sb = (size_t)t * 2 * MSZ;
#pragma unroll
    for (int q = 0; q < 16; q++) {
        int e = tid + 256 * q;
        __nv_bfloat16 hh, ll;
        split2(sA[e], hh, ll);
        g_powsb[sb + e] = hh;
        g_powsb[sb + MSZ + e] = ll;
    }
}

// ===========================================================================
// Kernel 4: HMMA gemm (R14 base: 1 CTA/SM, full A caching, cp.async,
// triplet MMA order) + SMEM EPILOGUE:
//   fragments -> STS (smem crossbar, not the gmem L1 FIFO)
//   -> barrier -> coalesced LDS.128/STG.128 copy (full 128B lines,
//   256 wf/iter = minimum; was 1024 scattered wf blocking next LDSMs).
// Epilogue buffer double-buffered to avoid cross-iter races.
// ===========================================================================
#define ASTRIDE 144
#define A_PLANE 18432
#define B_PLANE 9216
#define SM_B    (2 * A_PLANE)       // 36864
#define B_BUF   (2 * B_PLANE)       // 18432
#define SM_EP   (SM_B + 2 * B_BUF)  // 73728
#define EP_STRIDE 68                // floats per padded epilogue row
#define EP_SZ   (128 * EP_STRIDE * 4)   // 34816
#define SM_TOT  (SM_EP + 2 * EP_SZ)     // 143360

__global__ __launch_bounds__(256, 1)
void gemm_mma_kernel(float* __restrict__ out) {
    extern __shared__ char smc[];
    uint32_t sbase = smem_to_u32(smc);
    int tid = threadIdx.x;
    int w = tid >> 5, lane = tid & 31;
    int rg = w & 3;          // rows 32*rg .. +32
    int cg = w >> 2;         // cols 32*cg .. +32
    int b0 = blockIdx.x << 7;
    int tbase = blockIdx.y * TLOOP;

    // ---- stage A via cp.async: 2 planes x 128 rows x 64 bf16 ----
#pragma unroll
    for (int q = 0; q < 8; q++) {
        int e = tid + 256 * q;
        int p = e >> 10, rem = e & 1023;
        int row = rem >> 3, c = rem & 7;
        CP_ASYNC16(sbase + p * A_PLANE + row * ASTRIDE + c * 16,
                   g_x0s + p * (BATCH * DIM) + (b0 + row) * 64 + c * 8);
    }
    // ---- stage B buffer 0 via cp.async ----
    {
        const __nv_bfloat16* src = g_powsb + (size_t)tbase * 2 * MSZ;
#pragma unroll
        for (int q = 0; q < 4; q++) {
            int e = tid + 256 * q;
            int p = e >> 9, rem = e & 511;
            int row = rem >> 3, c = rem & 7;
            CP_ASYNC16(sbase + SM_B + p * B_PLANE + row * ASTRIDE + c * 16,
                       src + p * MSZ + row * 64 + c * 8);
        }
    }
    CP_COMMIT();
    CP_WAIT0();
    __syncthreads();

    // ---- A fragments fully cached: 2 m-tiles x 4 k x 2 planes ----
    uint32_t aH[2][4][4], aL[2][4][4];
#pragma unroll
    for (int mt = 0; mt < 2; mt++) {
        uint32_t arow = sbase + (32 * rg + 16 * mt + (lane & 15)) * ASTRIDE
                      + (lane >> 4) * 16;
#pragma unroll
        for (int k = 0; k < 4; k++) {
            LDSM_X4(aH[mt][k], arow + k * 32);
            LDSM_X4(aL[mt][k], arow + A_PLANE + k * 32);
        }
    }

    uint32_t brow_off = (32 * cg + ((lane >> 4) << 3) + (lane & 7)) * ASTRIDE
                      + ((lane >> 3) & 1) * 16;

    // epilogue addressing
    float* ep0 = (float*)(smc + SM_EP);
    float* ep1 = (float*)(smc + SM_EP + EP_SZ);
    int g = lane >> 2, tq = lane & 3;
    // copy-out: warp w owns rows [16w, 16w+16); lane: 2 rows x 16 lanes
    int cp_row = 16 * w + (lane >> 4);     // + 2*rr
    int cp_col = (lane & 15) * 4;

    int cur = 0;
#pragma unroll 1
    for (int it = 0; it < TLOOP; it++) {
        int t = tbase + it;

        // ---- prefetch next B via cp.async ----
        if (it + 1 < TLOOP) {
            const __nv_bfloat16* src = g_powsb + (size_t)(t + 1) * 2 * MSZ;
#pragma unroll
            for (int q = 0; q < 4; q++) {
                int e = tid + 256 * q;
                int p = e >> 9, rem = e & 511;
                int row = rem >> 3, c = rem & 7;
                CP_ASYNC16(sbase + SM_B + (1 - cur) * B_BUF + p * B_PLANE
                           + row * ASTRIDE + c * 16,
                           src + p * MSZ + row * 64 + c * 8);
            }
        }
        CP_COMMIT();

        float acc[2][4][4];
#pragma unroll
        for (int mt = 0; mt < 2; mt++)
#pragma unroll
            for (int nt = 0; nt < 4; nt++)
#pragma unroll
                for (int c = 0; c < 4; c++) acc[mt][nt][c] = 0.0f;

        uint32_t bb = sbase + SM_B + cur * B_BUF + brow_off;
#pragma unroll
        for (int k = 0; k < 4; k++) {
            uint32_t bH[4][2], bL[4][2];
#pragma unroll
            for (int p = 0; p < 2; p++) {
                uint32_t addr = bb + p * 16 * ASTRIDE + k * 32;
                LDSM_X4(&bH[2 * p][0], addr);
                LDSM_X4(&bL[2 * p][0], addr + B_PLANE);
            }
#pragma unroll
            for (int mt = 0; mt < 2; mt++)
#pragma unroll
                for (int nt = 0; nt < 4; nt++) {
                    MMA16816(acc[mt][nt], aH[mt][k], bH[nt]);
                    MMA16816(acc[mt][nt], aH[mt][k], bL[nt]);
                    MMA16816(acc[mt][nt], aL[mt][k], bH[nt]);
                }
        }

        // ---- STS fragments to epilogue buffer (smem crossbar) ----
        float* ep = cur ? ep1 : ep0;
#pragma unroll
        for (int mt = 0; mt < 2; mt++) {
            int r0 = 32 * rg + 16 * mt + g;
#pragma unroll
            for (int nt = 0; nt < 4; nt++) {
                int col = 32 * cg + 8 * nt + 2 * tq;
                *(float2*)(ep + r0 * EP_STRIDE + col) =
                    make_float2(acc[mt][nt][0], acc[mt][nt][1]);
                *(float2*)(ep + (r0 + 8) * EP_STRIDE + col) =
                    make_float2(acc[mt][nt][2], acc[mt][nt][3]);
            }
        }

        CP_WAIT0();        // next B buffer landed
        __syncthreads();   // B reads done + STS visible to all warps

        // ---- coalesced copy-out: LDS.128 -> STG.128 (full 128B lines) ----
#pragma unroll
        for (int rr = 0; rr < 8; rr++) {
            int row = cp_row + 2 * rr;
            float4 v = *(float4*)(ep + row * EP_STRIDE + cp_col);
            *(float4*)(out + ((size_t)(b0 + row) * TSTEPS + t) * DIM + cp_col) = v;
        }

        cur ^= 1;
    }
}

// ===========================================================================
extern "C" void kernel_launch(void* const* d_in, const int* in_sizes, int n_in,
                              void* d_out, int out_size) {
    const float* inputs = (const float*)d_in[0];
    const float* kern   = (const float*)d_in[1];
    if (in_sizes[0] == MSZ) {   // defensive: metadata order swap
        const float* tmp = inputs; inputs = kern; kern = tmp;
    }
    float* out = (float*)d_out;

    cudaFuncSetAttribute(expm_sq_kernel, cudaFuncAttributeMaxDynamicSharedMemorySize,
                         L1_SMEM);
    cudaFuncSetAttribute(tables_kernel, cudaFuncAttributeMaxDynamicSharedMemorySize,
                         L_TB_SMEM);
    cudaFuncSetAttribute(power_kernel, cudaFuncAttributeMaxDynamicSharedMemorySize,
                         L_PW_SMEM);
    cudaFuncSetAttribute(gemm_mma_kernel, cudaFuncAttributeMaxDynamicSharedMemorySize,
                         SM_TOT);

    expm_sq_kernel<<<257, 256, L1_SMEM>>>(kern, inputs);
    tables_kernel<<<64, 256, L_TB_SMEM>>>();
    power_kernel<<<TSTEPS, 256, L_PW_SMEM>>>();

    dim3 grid(BATCH / 128, TSTEPS / TLOOP);   // (8, 125)
    gemm_mma_kernel<<<grid, 256, SM_TOT>>>(out);
}

// round 17
// speedup vs baseline: 1.0773x; 1.0773x over previous
#include <cuda_runtime.h>
#include <cuda_bf16.h>
#include <cstdint>

#define DIM 64
#define TSTEPS 1000
#define BATCH 1024
#define MSZ (DIM*DIM)   // 4096

// squaring table M^(2^j), j = 0..9, fp32
__device__ float g_sq[10 * MSZ];
// two-level tables: low[r] = M^r (r<32), high[q] = M^(32q) (q<32)
__device__ float g_low[32 * MSZ];
__device__ float g_high[32 * MSZ];
// bf16 2-way split of x0: [plane][b*64+j]
__device__ __align__(16) __nv_bfloat16 g_x0s[2 * BATCH * DIM];

// ===========================================================================
// helpers
// ===========================================================================
__device__ __forceinline__ uint32_t smem_to_u32(const void* p) {
    uint32_t a;
    asm("{ .reg .u64 t; cvta.to.shared.u64 t, %1; cvt.u32.u64 %0, t; }"
        : "=r"(a) : "l"(p));
    return a;
}

__device__ __forceinline__ void split2(float v, __nv_bfloat16& h, __nv_bfloat16& l) {
    h = __float2bfloat16(v);
    l = __float2bfloat16(v - __bfloat162float(h));
}
__device__ __forceinline__ void split3(float v, __nv_bfloat16& h,
                                       __nv_bfloat16& m, __nv_bfloat16& l) {
    h = __float2bfloat16(v);
    float r = v - __bfloat162float(h);
    m = __float2bfloat16(r);
    l = __float2bfloat16(r - __bfloat162float(m));
}

#define LDSM_X4(r, addr) \
    asm volatile("ldmatrix.sync.aligned.m8n8.x4.shared.b16 {%0,%1,%2,%3}, [%4];" \
        : "=r"((r)[0]), "=r"((r)[1]), "=r"((r)[2]), "=r"((r)[3]) : "r"(addr))

#define LDSM_X4_T(r, addr) \
    asm volatile("ldmatrix.sync.aligned.m8n8.x4.trans.shared.b16 {%0,%1,%2,%3}, [%4];" \
        : "=r"((r)[0]), "=r"((r)[1]), "=r"((r)[2]), "=r"((r)[3]) : "r"(addr))

#define MMA16816(d, a, b) \
    asm volatile("mma.sync.aligned.m16n8k16.row.col.f32.bf16.bf16.f32 " \
        "{%0,%1,%2,%3}, {%4,%5,%6,%7}, {%8,%9}, {%0,%1,%2,%3};" \
        : "+f"((d)[0]), "+f"((d)[1]), "+f"((d)[2]), "+f"((d)[3]) \
        : "r"((a)[0]), "r"((a)[1]), "r"((a)[2]), "r"((a)[3]), \
          "r"((b)[0]), "r"((b)[1]))

// cp.async: 16B global -> shared, bypassing registers
#define CP_ASYNC16(dst_u32, src_ptr) \
    asm volatile("cp.async.ca.shared.global [%0], [%1], 16;" \
        :: "r"(dst_u32), "l"(src_ptr))
#define CP_COMMIT()  asm volatile("cp.async.commit_group;" ::: "memory")
#define CP_WAIT0()   asm volatile("cp.async.wait_group 0;" ::: "memory")

#define PL 9216     // plane bytes: 64 rows * 144

// ===========================================================================
// mm64_tc3: C = A @ B via 3-way bf16 split + 6-cross HMMA (~1.5e-8/multiply).
// 256 threads. C may alias A/B. scr: 6 planes = 55296B.
// ===========================================================================
#define SCR3_SZ (6 * PL)
__device__ void mm64_tc3(const float* A, const float* B, float* C, char* scr) {
    uint32_t scrb = smem_to_u32(scr);
    int tid = threadIdx.x;
    __syncthreads();
#pragma unroll
    for (int q = 0; q < 8; q++) {
        int e2 = tid + 256 * q;
        int row = e2 >> 5, cp = e2 & 31;
        float2 a = *(const float2*)(A + row * 64 + cp * 2);
        float2 b = *(const float2*)(B + row * 64 + cp * 2);
        __nv_bfloat16 h0, m0, l0, h1, m1, l1;
        split3(a.x, h0, m0, l0); split3(a.y, h1, m1, l1);
        *(__nv_bfloat162*)(scr + 0 * PL + row * 144 + cp * 4) = {h0, h1};
        *(__nv_bfloat162*)(scr + 1 * PL + row * 144 + cp * 4) = {m0, m1};
        *(__nv_bfloat162*)(scr + 2 * PL + row * 144 + cp * 4) = {l0, l1};
        split3(b.x, h0, m0, l0); split3(b.y, h1, m1, l1);
        *(__nv_bfloat162*)(scr + 3 * PL + row * 144 + cp * 4) = {h0, h1};
        *(__nv_bfloat162*)(scr + 4 * PL + row * 144 + cp * 4) = {m0, m1};
        *(__nv_bfloat162*)(scr + 5 * PL + row * 144 + cp * 4) = {l0, l1};
    }
    __syncthreads();
    int w = tid >> 5, lane = tid & 31;
    int mt = w & 3, nh = w >> 2;
    float acc[4][4];
#pragma unroll
    for (int nt = 0; nt < 4; nt++)
#pragma unroll
        for (int c = 0; c < 4; c++) acc[nt][c] = 0.0f;

    uint32_t a_base = scrb + (16 * mt + (lane & 15)) * 144 + ((lane >> 4) * 8) * 2;
#pragma unroll
    for (int k0 = 0; k0 < 64; k0 += 16) {
        uint32_t aH[4], aM[4], aL[4];
        LDSM_X4(aH, a_base + k0 * 2);
        LDSM_X4(aM, a_base + PL + k0 * 2);
        LDSM_X4(aL, a_base + 2 * PL + k0 * 2);
#pragma unroll
        for (int np = 0; np < 2; np++) {
            int n0 = 32 * nh + np * 16;
            uint32_t b_addr = scrb + 3 * PL + (k0 + (lane & 15)) * 144
                            + (n0 + (lane >> 4) * 8) * 2;
            uint32_t bH[4], bM[4], bL[4];
            LDSM_X4_T(bH, b_addr);
            LDSM_X4_T(bM, b_addr + PL);
            LDSM_X4_T(bL, b_addr + 2 * PL);
#pragma unroll
            for (int h2 = 0; h2 < 2; h2++) {
                float* d = acc[2 * np + h2];
                MMA16816(d, aH, &bH[2 * h2]);
                MMA16816(d, aH, &bM[2 * h2]);
                MMA16816(d, aM, &bH[2 * h2]);
                MMA16816(d, aH, &bL[2 * h2]);
                MMA16816(d, aM, &bM[2 * h2]);
                MMA16816(d, aL, &bH[2 * h2]);
            }
        }
    }
    __syncthreads();
    int g = lane >> 2, qd = lane & 3;
#pragma unroll
    for (int nt = 0; nt < 4; nt++) {
        int col = 32 * nh + 8 * nt + 2 * qd;
        *(float2*)(C + (16 * mt + g) * 64 + col) = make_float2(acc[nt][0], acc[nt][1]);
        *(float2*)(C + (16 * mt + g + 8) * 64 + col) = make_float2(acc[nt][2], acc[nt][3]);
    }
    __syncthreads();
}

// ===========================================================================
// mm64_tc2_to_planes: bf16 planes(hi/lo, padded 144B rows) = split2(A @ B),
// via 2-way bf16 split + 3-cross HMMA. A,B fp32 row-major (gmem ok).
// 256 threads. scr: 4 planes = 36864B. Result never touches fp32 smem.
// ===========================================================================
#define SCR2_SZ (4 * PL)
__device__ void mm64_tc2_to_planes(const float* A, const float* B,
                                   char* planes, char* scr) {
    uint32_t scrb = smem_to_u32(scr);
    int tid = threadIdx.x;
    __syncthreads();
#pragma unroll
    for (int q = 0; q < 8; q++) {
        int e2 = tid + 256 * q;
        int row = e2 >> 5, cp = e2 & 31;
        float2 a = *(const float2*)(A + row * 64 + cp * 2);
        float2 b = *(const float2*)(B + row * 64 + cp * 2);
        __nv_bfloat16 h0, l0, h1, l1;
        split2(a.x, h0, l0); split2(a.y, h1, l1);
        *(__nv_bfloat162*)(scr + 0 * PL + row * 144 + cp * 4) = {h0, h1};
        *(__nv_bfloat162*)(scr + 1 * PL + row * 144 + cp * 4) = {l0, l1};
        split2(b.x, h0, l0); split2(b.y, h1, l1);
        *(__nv_bfloat162*)(scr + 2 * PL + row * 144 + cp * 4) = {h0, h1};
        *(__nv_bfloat162*)(scr + 3 * PL + row * 144 + cp * 4) = {l0, l1};
    }
    __syncthreads();
    int w = tid >> 5, lane = tid & 31;
    int mt = w & 3, nh = w >> 2;
    float acc[4][4];
#pragma unroll
    for (int nt = 0; nt < 4; nt++)
#pragma unroll
        for (int c = 0; c < 4; c++) acc[nt][c] = 0.0f;

    uint32_t a_base = scrb + (16 * mt + (lane & 15)) * 144 + ((lane >> 4) * 8) * 2;
#pragma unroll
    for (int k0 = 0; k0 < 64; k0 += 16) {
        uint32_t aH[4], aL[4];
        LDSM_X4(aH, a_base + k0 * 2);
        LDSM_X4(aL, a_base + PL + k0 * 2);
#pragma unroll
        for (int np = 0; np < 2; np++) {
            int n0 = 32 * nh + np * 16;
            uint32_t b_addr = scrb + 2 * PL + (k0 + (lane & 15)) * 144
                            + (n0 + (lane >> 4) * 8) * 2;
            uint32_t bH[4], bL[4];
            LDSM_X4_T(bH, b_addr);
            LDSM_X4_T(bL, b_addr + PL);
#pragma unroll
            for (int h2 = 0; h2 < 2; h2++) {
                float* d = acc[2 * np + h2];
                MMA16816(d, aH, &bH[2 * h2]);
                MMA16816(d, aH, &bL[2 * h2]);
                MMA16816(d, aL, &bH[2 * h2]);
            }
        }
    }
    __syncthreads();   // scratch consumed; planes may alias nothing here
    int g = lane >> 2, qd = lane & 3;
#pragma unroll
    for (int nt = 0; nt < 4; nt++) {
        int col = 32 * nh + 8 * nt + 2 * qd;
        __nv_bfloat16 h0, l0, h1, l1;
        split2(acc[nt][0], h0, l0); split2(acc[nt][1], h1, l1);
        *(__nv_bfloat162*)(planes + (16 * mt + g) * 144 + col * 2) = {h0, h1};
        *(__nv_bfloat162*)(planes + PL + (16 * mt + g) * 144 + col * 2) = {l0, l1};
        split2(acc[nt][2], h0, l0); split2(acc[nt][3], h1, l1);
        *(__nv_bfloat162*)(planes + (16 * mt + g + 8) * 144 + col * 2) = {h0, h1};
        *(__nv_bfloat162*)(planes + PL + (16 * mt + g + 8) * 144 + col * 2) = {l0, l1};
    }
    __syncthreads();
}

// ===========================================================================
// Kernel 1 (grid 257): CTA 0: M = expm(K) (deg-8 PS Taylor) + 9 squarings
// (3-way tc). CTAs 1..256: x0 bf16 split.
// ===========================================================================
#define L1_SMEM (5 * MSZ * 4 + SCR3_SZ)
__global__ void expm_sq_kernel(const float* __restrict__ Kin,
                               const float* __restrict__ inputs) {
    int tid = threadIdx.x;
    if (blockIdx.x > 0) {   // x0 split
        int idx = (int)(blockIdx.x - 1) * 256 + tid;   // 0..65535
        int b = idx >> 6, j = idx & 63;
        float v = inputs[(size_t)b * (TSTEPS * DIM) + j];
        __nv_bfloat16 h, l;
        split2(v, h, l);
        g_x0s[idx] = h;
        g_x0s[65536 + idx] = l;
        return;
    }

    extern __shared__ float smf[];
    float* sK  = smf;
    float* sK2 = smf + MSZ;
    float* sK3 = smf + 2 * MSZ;
    float* sS  = smf + 3 * MSZ;
    float* sT  = smf + 4 * MSZ;
    char* scr = (char*)(smf + 5 * MSZ);

    // 1/n! for n = 0..8
    const float c[9] = {
        1.0f, 1.0f, 0.5f,
        1.6666666666666666e-1f, 4.1666666666666664e-2f, 8.3333333333333332e-3f,
        1.3888888888888889e-3f, 1.9841269841269841e-4f, 2.4801587301587302e-5f
    };

#pragma unroll
    for (int q = 0; q < 16; q++) sK[tid + 256 * q] = Kin[tid + 256 * q];

    mm64_tc3(sK, sK, sK2, scr);     // K^2
    mm64_tc3(sK2, sK, sK3, scr);    // K^3

    // S = B2 = c6 I + c7 K + c8 K^2
#pragma unroll
    for (int q = 0; q < 16; q++) {
        int e = tid + 256 * q;
        int i = e >> 6, j = e & 63;
        sS[e] = (i == j ? c[6] : 0.0f) + c[7] * sK[e] + c[8] * sK2[e];
    }
    __syncthreads();
    for (int m = 1; m >= 0; m--) {
        mm64_tc3(sK3, sS, sT, scr);
#pragma unroll
        for (int q = 0; q < 16; q++) {
            int e = tid + 256 * q;
            int i = e >> 6, j = e & 63;
            sS[e] = sT[e] + (i == j ? c[3 * m] : 0.0f)
                  + c[3 * m + 1] * sK[e] + c[3 * m + 2] * sK2[e];
        }
        __syncthreads();
    }

    // sS = M. Store sq[0], then 9 squarings (in-place safe).
#pragma unroll
    for (int q = 0; q < 16; q++) g_sq[tid + 256 * q] = sS[tid + 256 * q];
    for (int j = 1; j <= 9; j++) {
        mm64_tc3(sS, sS, sS, scr);
#pragma unroll
        for (int q = 0; q < 16; q++)
            g_sq[j * MSZ + tid + 256 * q] = sS[tid + 256 * q];
    }
}

// ===========================================================================
// Kernel 2 (grid 64): two-level tables (3-way tc).
//   bid < 32 : g_low[bid]     = M^bid
//   bid >= 32: g_high[bid-32] = M^(32(bid-32))
// ===========================================================================
#define L_TB_SMEM (MSZ * 4 + SCR3_SZ)
__global__ void tables_kernel() {
    extern __shared__ float smf[];
    float* sA = smf;
    char* scr = (char*)(smf + MSZ);
    int bid = blockIdx.x;
    int tid = threadIdx.x;

    int n = bid & 31;
    int base = (bid < 32) ? 0 : 5;
    float* dst = (bid < 32 ? g_low : g_high) + (size_t)n * MSZ;

    if (n == 0) {
#pragma unroll
        for (int q = 0; q < 16; q++) {
            int e = tid + 256 * q;
            dst[e] = ((e >> 6) == (e & 63)) ? 1.0f : 0.0f;
        }
        return;
    }

    int j0 = __ffs(n) - 1;
    const float* first = g_sq + (size_t)(base + j0) * MSZ;
    bool in_smem = false;
    for (int j = j0 + 1; j < 5; j++) {
        if ((n >> j) & 1) {
            const float* fac = g_sq + (size_t)(base + j) * MSZ;
            mm64_tc3(in_smem ? sA : first, fac, sA, scr);
            in_smem = true;
        }
    }
    const float* res = in_smem ? sA : first;
#pragma unroll
    for (int q = 0; q < 16; q++) {
        int e = tid + 256 * q;
        dst[e] = res[e];
    }
}

// ===========================================================================
// Kernel 3: FUSED power + gemm. grid(1000) = one CTA per t.
//   1. issue cp.async for x0 chunk 0 (overlaps step 2)
//   2. M^t = high[t>>5] @ low[t&31] -> bf16 hi/lo planes directly in smem
//   3. cache B (M^t) fragments in registers, once (64 regs)
//   4. loop 8 batch chunks of 128: stream A (x0) via cp.async double buffer,
//      R14-proven inner loop (triplet MMA order, stores pre-barrier).
// Eliminates power_kernel launch + entire g_powsb gmem round-trip.
// x0 splits (256KB) are L2-resident across all CTAs.
// ===========================================================================
#define A_CH  36864                 // one A chunk: 2 planes x 128 rows x 144B
#define A_PLN 18432                 // plane stride within an A chunk
#define SM_BP (2 * A_CH)            // 73728: B planes (hi/lo)
#define SMF_TOT (SM_BP + 2 * PL)    // 92160

__global__ __launch_bounds__(256, 1)
void gemm_fused_kernel(float* __restrict__ out) {
    extern __shared__ char smc[];
    uint32_t sbase = smem_to_u32(smc);
    int tid = threadIdx.x;
    int w = tid >> 5, lane = tid & 31;
    int rg = w & 3;          // rows 32*rg .. +32 (within 128-chunk)
    int cg = w >> 2;         // cols 32*cg .. +32
    int t = blockIdx.x;

    // ---- 1. issue chunk 0 A-loads into buf0 (independent of M^t compute) ----
#pragma unroll
    for (int q = 0; q < 8; q++) {
        int e = tid + 256 * q;          // 0..2047
        int p = e >> 10, rem = e & 1023;
        int row = rem >> 3, cc = rem & 7;
        CP_ASYNC16(sbase + p * A_PLN + row * 144 + cc * 16,
                   g_x0s + p * (BATCH * DIM) + row * 64 + cc * 8);
    }
    CP_COMMIT();

    // ---- 2. M^t bf16 planes (scratch aliases A buf1: no cp.async targets it) ----
    mm64_tc2_to_planes(g_high + (size_t)(t >> 5) * MSZ,
                       g_low + (size_t)(t & 31) * MSZ,
                       smc + SM_BP, smc + A_CH);

    // ---- 3. cache B fragments (this warp's 32-col half), once ----
    uint32_t bb = sbase + SM_BP
                + (32 * cg + ((lane >> 4) << 3) + (lane & 7)) * 144
                + ((lane >> 3) & 1) * 16;
    uint32_t cbH[4][4][2], cbL[4][4][2];
#pragma unroll
    for (int k = 0; k < 4; k++)
#pragma unroll
        for (int p = 0; p < 2; p++) {
            LDSM_X4(&cbH[k][2 * p][0], bb + p * 16 * 144 + k * 32);
            LDSM_X4(&cbL[k][2 * p][0], bb + p * 16 * 144 + k * 32 + PL);
        }

    CP_WAIT0();
    __syncthreads();   // chunk 0 landed

    uint32_t a_off = (32 * rg + (lane & 15)) * 144 + (lane >> 4) * 16;
    int g = lane >> 2, tq = lane & 3;

    int cur = 0;
#pragma unroll 1
    for (int c0 = 0; c0 < 8; c0++) {
        int b0 = c0 << 7;

        // ---- prefetch next A chunk into other buffer ----
        if (c0 + 1 < 8) {
            int nb0 = (c0 + 1) << 7;
#pragma unroll
            for (int q = 0; q < 8; q++) {
                int e = tid + 256 * q;
                int p = e >> 10, rem = e & 1023;
                int row = rem >> 3, cc = rem & 7;
                CP_ASYNC16(sbase + (1 - cur) * A_CH + p * A_PLN + row * 144 + cc * 16,
                           g_x0s + p * (BATCH * DIM) + (nb0 + row) * 64 + cc * 8);
            }
        }
        CP_COMMIT();

        float acc[2][4][4];
#pragma unroll
        for (int mt = 0; mt < 2; mt++)
#pragma unroll
            for (int nt = 0; nt < 4; nt++)
#pragma unroll
                for (int c = 0; c < 4; c++) acc[mt][nt][c] = 0.0f;

        uint32_t ab = sbase + cur * A_CH + a_off;
#pragma unroll
        for (int k = 0; k < 4; k++) {
            uint32_t aH[2][4], aL[2][4];
#pragma unroll
            for (int mt = 0; mt < 2; mt++) {
                LDSM_X4(aH[mt], ab + mt * 16 * 144 + k * 32);
                LDSM_X4(aL[mt], ab + mt * 16 * 144 + k * 32 + A_PLN);
            }
            // R14-proven triplet order
#pragma unroll
            for (int mt = 0; mt < 2; mt++)
#pragma unroll
                for (int nt = 0; nt < 4; nt++) {
                    MMA16816(acc[mt][nt], aH[mt], cbH[k][nt]);
                    MMA16816(acc[mt][nt], aH[mt], cbL[k][nt]);
                    MMA16816(acc[mt][nt], aL[mt], cbH[k][nt]);
                }
        }

        // ---- stores PRE-barrier (drain during barrier wait; R14-proven) ----
#pragma unroll
        for (int mt = 0; mt < 2; mt++) {
            size_t b = (size_t)b0 + 32 * rg + 16 * mt + g;
            float* o0 = out + (b * TSTEPS + t) * DIM + 32 * cg + 2 * tq;
            float* o1 = o0 + (size_t)8 * TSTEPS * DIM;
#pragma unroll
            for (int nt = 0; nt < 4; nt++) {
                *(float2*)(o0 + nt * 8) = make_float2(acc[mt][nt][0], acc[mt][nt][1]);
                *(float2*)(o1 + nt * 8) = make_float2(acc[mt][nt][2], acc[mt][nt][3]);
            }
        }

        CP_WAIT0();        // next chunk landed
        __syncthreads();   // all reads of current buffer done before overwrite
        cur ^= 1;
    }
}

// ===========================================================================
extern "C" void kernel_launch(void* const* d_in, const int* in_sizes, int n_in,
                              void* d_out, int out_size) {
    const float* inputs = (const float*)d_in[0];
    const float* kern   = (const float*)d_in[1];
    if (in_sizes[0] == MSZ) {   // defensive: metadata order swap
        const float* tmp = inputs; inputs = kern; kern = tmp;
    }
    float* out = (float*)d_out;

    cudaFuncSetAttribute(expm_sq_kernel, cudaFuncAttributeMaxDynamicSharedMemorySize,
                         L1_SMEM);
    cudaFuncSetAttribute(tables_kernel, cudaFuncAttributeMaxDynamicSharedMemorySize,
                         L_TB_SMEM);
    cudaFuncSetAttribute(gemm_fused_kernel, cudaFuncAttributeMaxDynamicSharedMemorySize,
                         SMF_TOT);

    expm_sq_kernel<<<257, 256, L1_SMEM>>>(kern, inputs);
    tables_kernel<<<64, 256, L_TB_SMEM>>>();
    gemm_fused_kernel<<<TSTEPS, 256, SMF_TOT>>>(out);
}